// round 2
// baseline (speedup 1.0000x reference)
#include <cuda_runtime.h>

#define GRIDSZ 160
#define GRID3 (GRIDSZ*GRIDSZ*GRIDSZ)
#define NPTS 262144
#define CIN 64
#define COUT 96
#define TILE 64
#define TILES_PER_K 4096   /* NPTS / TILE */
#define LN_EPS 1e-5f

// ---------------- scratch (static device globals; no allocation) ----------------
__device__ int   g_grid[GRID3];                 // voxel -> point index (-1 empty), 16.4 MB
__device__ int   g_cnt[27];                     // pairs per offset
__device__ int2  g_pairs[27u * NPTS];           // (out_idx, in_idx) per offset, 56.6 MB
__device__ float g_conv[(size_t)NPTS * COUT];   // conv accumulator, 100.7 MB

// ---------------- 1) init grid to -1, zero counters ----------------
__global__ void k_init() {
    int tid = blockIdx.x * blockDim.x + threadIdx.x;
    if (tid < 27) g_cnt[tid] = 0;
    int4* g4 = (int4*)g_grid;
    const int n4 = GRID3 / 4;
    const int stride = gridDim.x * blockDim.x;
    int4 m1 = make_int4(-1, -1, -1, -1);
    for (int i = tid; i < n4; i += stride) g4[i] = m1;
}

// ---------------- 2) scatter point indices (last-write-wins via atomicMax) ------
__global__ void k_scatter(const int* __restrict__ coords) {
    int i = blockIdx.x * blockDim.x + threadIdx.x;
    if (i < NPTS) {
        int z = coords[3*i+0], y = coords[3*i+1], x = coords[3*i+2];
        atomicMax(&g_grid[(z*GRIDSZ + y)*GRIDSZ + x], i);
    }
}

// ---------------- 3) build per-offset pair lists (skip center k=13) -------------
__global__ __launch_bounds__(256) void k_build_pairs(const int* __restrict__ coords) {
    __shared__ int s_warpcnt[8];
    __shared__ int s_woff[8];
    __shared__ int s_base;

    int tid  = threadIdx.x;
    int p    = blockIdx.x * 256 + tid;
    int warp = tid >> 5, lane = tid & 31;

    int z = coords[3*p+0], y = coords[3*p+1], x = coords[3*p+2];

    for (int k = 0; k < 27; ++k) {
        if (k == 13) continue;   // center handled densely
        int dz = k/9 - 1, dy = (k/3)%3 - 1, dx = k%3 - 1;
        int zz = z + dz, yy = y + dy, xx = x + dx;
        int nidx = -1;
        if ((unsigned)zz < GRIDSZ && (unsigned)yy < GRIDSZ && (unsigned)xx < GRIDSZ)
            nidx = g_grid[(zz*GRIDSZ + yy)*GRIDSZ + xx];
        bool valid = (nidx >= 0);

        unsigned m = __ballot_sync(0xffffffffu, valid);
        if (lane == 0) s_warpcnt[warp] = __popc(m);
        __syncthreads();
        if (tid == 0) {
            int tot = 0;
            #pragma unroll
            for (int w = 0; w < 8; ++w) { s_woff[w] = tot; tot += s_warpcnt[w]; }
            s_base = tot ? atomicAdd(&g_cnt[k], tot) : 0;
        }
        __syncthreads();
        if (valid) {
            int rank = __popc(m & ((1u << lane) - 1u));
            g_pairs[k * NPTS + s_base + s_woff[warp] + rank] = make_int2(p, nidx);
        }
        __syncthreads();   // protect smem reuse next k
    }
}

// ---------------- 4) center tap: dense tiled GEMM, plain stores (+bias) ---------
__global__ __launch_bounds__(256) void k_center_gemm(const float* __restrict__ feats,
                                                     const int*   __restrict__ coords,
                                                     const float* __restrict__ weight,
                                                     const float* __restrict__ bias) {
    __shared__ float sA[TILE][CIN + 4];    // 64 x 68
    __shared__ float sB[CIN][COUT + 4];    // 64 x 100
    __shared__ int   s_nin[TILE];

    const int tid  = threadIdx.x;
    const int base = blockIdx.x * TILE;

    if (tid < TILE) {
        int p = base + tid;
        int z = coords[3*p+0], y = coords[3*p+1], x = coords[3*p+2];
        s_nin[tid] = g_grid[(z*GRIDSZ + y)*GRIDSZ + x];   // collision winner (may != p)
    }
    __syncthreads();

    // gather features: 4 threads per row, 16 floats each
    {
        int row = tid >> 2, q = tid & 3;
        int ni = s_nin[row];
        float4* dst = (float4*)&sA[row][q * 16];
        if (ni >= 0) {
            const float4* src = (const float4*)(feats + (size_t)ni * CIN + q * 16);
            #pragma unroll
            for (int j = 0; j < 4; ++j) dst[j] = src[j];
        } else {
            float4 z4 = make_float4(0.f, 0.f, 0.f, 0.f);
            #pragma unroll
            for (int j = 0; j < 4; ++j) dst[j] = z4;
        }
    }
    // weight[13]: 64x96, 4 threads per row, 24 floats each
    {
        int row = tid >> 2, part = tid & 3;
        const float4* src = (const float4*)(weight + ((size_t)13 * CIN + row) * COUT + part * 24);
        float4* dst = (float4*)&sB[row][part * 24];
        #pragma unroll
        for (int j = 0; j < 6; ++j) dst[j] = src[j];
    }
    __syncthreads();

    const int tc = tid & 15, tr = tid >> 4;   // 16 col-groups x 16 row-groups
    float acc[4][6];
    #pragma unroll
    for (int r = 0; r < 4; ++r)
        #pragma unroll
        for (int c = 0; c < 6; ++c) acc[r][c] = 0.f;

    #pragma unroll 4
    for (int kk = 0; kk < CIN; ++kk) {
        float a0 = sA[tr*4+0][kk], a1 = sA[tr*4+1][kk];
        float a2 = sA[tr*4+2][kk], a3 = sA[tr*4+3][kk];
        float b[6];
        #pragma unroll
        for (int c = 0; c < 6; ++c) b[c] = sB[kk][tc*6 + c];
        #pragma unroll
        for (int c = 0; c < 6; ++c) {
            acc[0][c] += a0 * b[c];
            acc[1][c] += a1 * b[c];
            acc[2][c] += a2 * b[c];
            acc[3][c] += a3 * b[c];
        }
    }

    #pragma unroll
    for (int r = 0; r < 4; ++r) {
        int p = base + tr*4 + r;
        float* dst = g_conv + (size_t)p * COUT + tc*6;
        #pragma unroll
        for (int c = 0; c < 6; ++c) dst[c] = acc[r][c] + bias[tc*6 + c];
    }
}

// ---------------- 5) non-center taps: GEMM over pair list, atomicAdd ------------
__global__ __launch_bounds__(256) void k_offset_gemm(const float* __restrict__ feats,
                                                     const float* __restrict__ weight) {
    const int k    = blockIdx.x / TILES_PER_K;
    const int tile = blockIdx.x % TILES_PER_K;
    if (k == 13) return;
    const int cnt   = g_cnt[k];
    const int rbase = tile * TILE;
    if (rbase >= cnt) return;

    __shared__ float sA[TILE][CIN + 4];
    __shared__ float sB[CIN][COUT + 4];
    __shared__ int   s_out[TILE];
    __shared__ int   s_nin[TILE];

    const int tid = threadIdx.x;
    if (tid < TILE) {
        int i = rbase + tid;
        if (i < cnt) { int2 pr = g_pairs[k * NPTS + i]; s_out[tid] = pr.x; s_nin[tid] = pr.y; }
        else         { s_out[tid] = -1;                 s_nin[tid] = -1; }
    }
    __syncthreads();

    {
        int row = tid >> 2, q = tid & 3;
        int ni = s_nin[row];
        float4* dst = (float4*)&sA[row][q * 16];
        if (ni >= 0) {
            const float4* src = (const float4*)(feats + (size_t)ni * CIN + q * 16);
            #pragma unroll
            for (int j = 0; j < 4; ++j) dst[j] = src[j];
        } else {
            float4 z4 = make_float4(0.f, 0.f, 0.f, 0.f);
            #pragma unroll
            for (int j = 0; j < 4; ++j) dst[j] = z4;
        }
    }
    {
        int row = tid >> 2, part = tid & 3;
        const float4* src = (const float4*)(weight + ((size_t)k * CIN + row) * COUT + part * 24);
        float4* dst = (float4*)&sB[row][part * 24];
        #pragma unroll
        for (int j = 0; j < 6; ++j) dst[j] = src[j];
    }
    __syncthreads();

    const int tc = tid & 15, tr = tid >> 4;
    float acc[4][6];
    #pragma unroll
    for (int r = 0; r < 4; ++r)
        #pragma unroll
        for (int c = 0; c < 6; ++c) acc[r][c] = 0.f;

    #pragma unroll 4
    for (int kk = 0; kk < CIN; ++kk) {
        float a0 = sA[tr*4+0][kk], a1 = sA[tr*4+1][kk];
        float a2 = sA[tr*4+2][kk], a3 = sA[tr*4+3][kk];
        float b[6];
        #pragma unroll
        for (int c = 0; c < 6; ++c) b[c] = sB[kk][tc*6 + c];
        #pragma unroll
        for (int c = 0; c < 6; ++c) {
            acc[0][c] += a0 * b[c];
            acc[1][c] += a1 * b[c];
            acc[2][c] += a2 * b[c];
            acc[3][c] += a3 * b[c];
        }
    }

    #pragma unroll
    for (int r = 0; r < 4; ++r) {
        int op = s_out[tr*4 + r];
        if (op >= 0) {
            float* dst = g_conv + (size_t)op * COUT + tc*6;
            #pragma unroll
            for (int c = 0; c < 6; ++c) atomicAdd(dst + c, acc[r][c]);
        }
    }
}

// ---------------- 6) LayerNorm + ReLU (one warp per point) ----------------------
__global__ __launch_bounds__(256) void k_ln_relu(const float* __restrict__ gamma,
                                                 const float* __restrict__ beta,
                                                 float* __restrict__ out) {
    const int row  = (blockIdx.x * 256 + threadIdx.x) >> 5;
    const int lane = threadIdx.x & 31;
    const float* src = g_conv + (size_t)row * COUT;
    float v0 = src[lane], v1 = src[lane + 32], v2 = src[lane + 64];
    float s  = v0 + v1 + v2;
    float sq = v0*v0 + v1*v1 + v2*v2;
    #pragma unroll
    for (int o = 16; o > 0; o >>= 1) {
        s  += __shfl_xor_sync(0xffffffffu, s,  o);
        sq += __shfl_xor_sync(0xffffffffu, sq, o);
    }
    float mean = s * (1.f / COUT);
    float var  = sq * (1.f / COUT) - mean * mean;
    float inv  = rsqrtf(var + LN_EPS);
    float* dst = out + (size_t)row * COUT;
    dst[lane]      = fmaxf((v0 - mean) * inv * gamma[lane]      + beta[lane],      0.f);
    dst[lane + 32] = fmaxf((v1 - mean) * inv * gamma[lane + 32] + beta[lane + 32], 0.f);
    dst[lane + 64] = fmaxf((v2 - mean) * inv * gamma[lane + 64] + beta[lane + 64], 0.f);
}

// ---------------- launch ---------------------------------------------------------
extern "C" void kernel_launch(void* const* d_in, const int* in_sizes, int n_in,
                              void* d_out, int out_size) {
    const float* feats  = (const float*)d_in[0];
    const int*   coords = (const int*)  d_in[1];
    const float* weight = (const float*)d_in[2];
    const float* bias   = (const float*)d_in[3];
    const float* gamma  = (const float*)d_in[4];
    const float* beta   = (const float*)d_in[5];
    float* out = (float*)d_out;

    k_init       <<<4096, 256>>>();
    k_scatter    <<<NPTS / 256, 256>>>(coords);
    k_build_pairs<<<NPTS / 256, 256>>>(coords);
    k_center_gemm<<<TILES_PER_K, 256>>>(feats, coords, weight, bias);
    k_offset_gemm<<<27 * TILES_PER_K, 256>>>(feats, weight);
    k_ln_relu    <<<NPTS / 8, 256>>>(gamma, beta, out);
}

// round 3
// speedup vs baseline: 1.5672x; 1.5672x over previous
#include <cuda_runtime.h>
#include <cuda_bf16.h>

#define GRIDSZ 160
#define GRID3 (GRIDSZ*GRIDSZ*GRIDSZ)
#define NPTS 262144
#define CIN 64
#define COUT 96
#define TILE 64
#define TILES_PER_K 4096   /* NPTS / TILE */
#define LN_EPS 1e-5f

// smem row stride in 32-bit words: 32 hi-words + 32 lo-words + 4 pad  (68 % 32 == 4)
#define RW 68

// ---------------- scratch (static device globals; no allocation) ----------------
__device__ int   g_grid[GRID3];                   // voxel -> point index (-1 empty)
__device__ int   g_cnt[27];                       // pairs per offset
__device__ int2  g_pairs[27u * NPTS];             // (out_idx, in_idx) per offset
__device__ float g_conv[(size_t)NPTS * COUT];     // conv accumulator
__device__ __nv_bfloat16 g_wprep[27 * 96 * 128];  // weights: [k][n][hi 0..63 | lo 64..127]

// ---------------- helpers --------------------------------------------------------
__device__ __forceinline__ void split2(float x, float y, unsigned& h, unsigned& l) {
    __nv_bfloat16 hx = __float2bfloat16_rn(x);
    __nv_bfloat16 hy = __float2bfloat16_rn(y);
    float rx = x - __bfloat162float(hx);
    float ry = y - __bfloat162float(hy);
    __nv_bfloat16 lx = __float2bfloat16_rn(rx);
    __nv_bfloat16 ly = __float2bfloat16_rn(ry);
    h = (unsigned)__bfloat16_as_ushort(hx) | ((unsigned)__bfloat16_as_ushort(hy) << 16);
    l = (unsigned)__bfloat16_as_ushort(lx) | ((unsigned)__bfloat16_as_ushort(ly) << 16);
}

__device__ __forceinline__ void mma16816(float* c, unsigned a0, unsigned a1,
                                         unsigned a2, unsigned a3,
                                         unsigned b0, unsigned b1) {
    asm volatile(
        "mma.sync.aligned.m16n8k16.row.col.f32.bf16.bf16.f32 "
        "{%0,%1,%2,%3}, {%4,%5,%6,%7}, {%8,%9}, {%0,%1,%2,%3};"
        : "+f"(c[0]), "+f"(c[1]), "+f"(c[2]), "+f"(c[3])
        : "r"(a0), "r"(a1), "r"(a2), "r"(a3), "r"(b0), "r"(b1));
}

// ---------------- 1) init grid to -1, zero counters ------------------------------
__global__ void k_init() {
    int tid = blockIdx.x * blockDim.x + threadIdx.x;
    if (tid < 27) g_cnt[tid] = 0;
    int4* g4 = (int4*)g_grid;
    const int n4 = GRID3 / 4;
    const int stride = gridDim.x * blockDim.x;
    int4 m1 = make_int4(-1, -1, -1, -1);
    for (int i = tid; i < n4; i += stride) g4[i] = m1;
}

// ---------------- 2) scatter point indices (last-write-wins via atomicMax) -------
__global__ void k_scatter(const int* __restrict__ coords) {
    int i = blockIdx.x * blockDim.x + threadIdx.x;
    if (i < NPTS) {
        int z = coords[3*i+0], y = coords[3*i+1], x = coords[3*i+2];
        atomicMax(&g_grid[(z*GRIDSZ + y)*GRIDSZ + x], i);
    }
}

// ---------------- 3) pre-split weights into bf16 hi/lo planes, n-major ----------
__global__ void k_prep_w(const float* __restrict__ w) {
    int t = blockIdx.x * 256 + threadIdx.x;
    if (t < 27 * CIN * COUT) {
        int k = t / (CIN * COUT);
        int r = t % (CIN * COUT);
        int c = r / COUT;          // cin
        int n = r % COUT;          // cout
        float x = w[t];
        __nv_bfloat16 hi = __float2bfloat16_rn(x);
        float rx = x - __bfloat162float(hi);
        __nv_bfloat16 lo = __float2bfloat16_rn(rx);
        g_wprep[(k * 96 + n) * 128 + c]      = hi;
        g_wprep[(k * 96 + n) * 128 + 64 + c] = lo;
    }
}

// ---------------- 4) build per-offset pair lists (skip center k=13) --------------
__global__ __launch_bounds__(256) void k_build_pairs(const int* __restrict__ coords) {
    __shared__ int s_wcnt[8];
    __shared__ int s_woff[8];
    __shared__ int s_base;

    const int tid  = threadIdx.x;
    const int p    = blockIdx.x * 256 + tid;
    const int warp = tid >> 5, lane = tid & 31;

    const int z = coords[3*p+0], y = coords[3*p+1], x = coords[3*p+2];

    // hoist all 26 probes (high MLP, all independent)
    int nidx[26];
    #pragma unroll
    for (int j = 0; j < 26; ++j) {
        const int k = (j < 13) ? j : j + 1;
        const int dz = k/9 - 1, dy = (k/3)%3 - 1, dx = k%3 - 1;
        int zz = z + dz, yy = y + dy, xx = x + dx;
        int ni = -1;
        if ((unsigned)zz < GRIDSZ && (unsigned)yy < GRIDSZ && (unsigned)xx < GRIDSZ)
            ni = g_grid[(zz*GRIDSZ + yy)*GRIDSZ + xx];
        nidx[j] = ni;
    }

    #pragma unroll
    for (int j = 0; j < 26; ++j) {
        const int k = (j < 13) ? j : j + 1;
        const bool valid = (nidx[j] >= 0);
        const unsigned m = __ballot_sync(0xffffffffu, valid);
        if (lane == 0) s_wcnt[warp] = __popc(m);
        __syncthreads();
        if (tid == 0) {
            int tot = 0;
            #pragma unroll
            for (int w = 0; w < 8; ++w) { s_woff[w] = tot; tot += s_wcnt[w]; }
            s_base = tot ? atomicAdd(&g_cnt[k], tot) : 0;
        }
        __syncthreads();
        if (valid) {
            int rank = __popc(m & ((1u << lane) - 1u));
            g_pairs[k * NPTS + s_base + s_woff[warp] + rank] = make_int2(p, nidx[j]);
        }
        // no 3rd barrier needed: s_wcnt rewrite is fenced by next iter's first barrier
    }
}

// ======================= shared GEMM-tile machinery ==============================
// Gather one 64-row feature tile into split-bf16 smem (hi words 0..31, lo 32..63)
__device__ __forceinline__ void gather_A(unsigned* sAw, const float* __restrict__ feats,
                                         const int* s_nin, int tid) {
    const int row = tid >> 2, q = tid & 3;
    const int ni = s_nin[row];
    unsigned* dh = &sAw[row * RW + q * 8];
    if (ni >= 0) {
        const float4* src = (const float4*)(feats + (size_t)ni * CIN + q * 16);
        #pragma unroll
        for (int j = 0; j < 4; ++j) {
            float4 v = src[j];
            unsigned h0, l0, h1, l1;
            split2(v.x, v.y, h0, l0);
            split2(v.z, v.w, h1, l1);
            dh[2*j]          = h0;
            dh[2*j + 1]      = h1;
            dh[2*j + 32]     = l0;
            dh[2*j + 33]     = l1;
        }
    } else {
        #pragma unroll
        for (int j = 0; j < 4; ++j) {
            dh[2*j] = 0u; dh[2*j+1] = 0u; dh[2*j+32] = 0u; dh[2*j+33] = 0u;
        }
    }
}

// Copy pre-split weight plane for offset k into smem
__device__ __forceinline__ void load_B(unsigned* sBw, int k, int tid) {
    const uint4* src = (const uint4*)&g_wprep[(size_t)k * 96 * 128];
    #pragma unroll
    for (int it = 0; it < 6; ++it) {
        int i = tid + it * 256;          // 0..1535
        int n = i >> 4, q = i & 15;      // 16 uint4 per 128-bf16 row
        *(uint4*)&sBw[n * RW + q * 4] = src[i];
    }
}

// Per-thread split-bf16 MMA mainloop: acc[6][4] += A(64x64) * B(64x96) sub-tile
__device__ __forceinline__ void mma_mainloop(const unsigned* sAw, const unsigned* sBw,
                                             float acc[6][4], int lane, int wm, int wn) {
    const int g = lane >> 2, tg = lane & 3;
    const int r0 = wm * 16 + g, r1 = r0 + 8;
    #pragma unroll
    for (int kb = 0; kb < 4; ++kb) {
        const int kw = kb * 8 + tg;
        const unsigned a0h = sAw[r0 * RW + kw],      a1h = sAw[r1 * RW + kw];
        const unsigned a2h = sAw[r0 * RW + kw + 4],  a3h = sAw[r1 * RW + kw + 4];
        const unsigned a0l = sAw[r0 * RW + kw + 32], a1l = sAw[r1 * RW + kw + 32];
        const unsigned a2l = sAw[r0 * RW + kw + 36], a3l = sAw[r1 * RW + kw + 36];
        #pragma unroll
        for (int nb = 0; nb < 6; ++nb) {
            const int n = wn * 48 + nb * 8 + g;
            const unsigned b0h = sBw[n * RW + kw],      b1h = sBw[n * RW + kw + 4];
            const unsigned b0l = sBw[n * RW + kw + 32], b1l = sBw[n * RW + kw + 36];
            mma16816(acc[nb], a0h, a1h, a2h, a3h, b0h, b1h);  // hi*hi
            mma16816(acc[nb], a0h, a1h, a2h, a3h, b0l, b1l);  // hi*lo
            mma16816(acc[nb], a0l, a1l, a2l, a3l, b0h, b1h);  // lo*hi
        }
    }
}

// ---------------- 5) center tap: dense GEMM, plain stores (+bias) ----------------
__global__ __launch_bounds__(256) void k_center_gemm(const float* __restrict__ feats,
                                                     const int*   __restrict__ coords,
                                                     const float* __restrict__ bias) {
    __shared__ unsigned sAw[64 * RW];
    __shared__ unsigned sBw[96 * RW];
    __shared__ int s_nin[TILE];

    const int tid  = threadIdx.x;
    const int base = blockIdx.x * TILE;

    if (tid < TILE) {
        int p = base + tid;
        int z = coords[3*p+0], y = coords[3*p+1], x = coords[3*p+2];
        s_nin[tid] = g_grid[(z*GRIDSZ + y)*GRIDSZ + x];   // cell winner (collision-aware)
    }
    __syncthreads();

    gather_A(sAw, feats, s_nin, tid);
    load_B(sBw, 13, tid);
    __syncthreads();

    const int lane = tid & 31, wid = tid >> 5;
    const int wm = wid & 3, wn = wid >> 2;
    float acc[6][4];
    #pragma unroll
    for (int nb = 0; nb < 6; ++nb)
        #pragma unroll
        for (int c = 0; c < 4; ++c) acc[nb][c] = 0.f;

    mma_mainloop(sAw, sBw, acc, lane, wm, wn);

    const int g = lane >> 2, tg = lane & 3;
    const int row0 = base + wm * 16 + g, row1 = row0 + 8;
    #pragma unroll
    for (int nb = 0; nb < 6; ++nb) {
        const int col = wn * 48 + nb * 8 + 2 * tg;
        const float b0 = __ldg(bias + col), b1 = __ldg(bias + col + 1);
        *(float2*)(g_conv + (size_t)row0 * COUT + col) =
            make_float2(acc[nb][0] + b0, acc[nb][1] + b1);
        *(float2*)(g_conv + (size_t)row1 * COUT + col) =
            make_float2(acc[nb][2] + b0, acc[nb][3] + b1);
    }
}

// ---------------- 6) non-center taps: GEMM over pair list, atomicAdd -------------
__global__ __launch_bounds__(256) void k_offset_gemm(const float* __restrict__ feats) {
    const int k    = blockIdx.x / TILES_PER_K;
    const int tile = blockIdx.x % TILES_PER_K;
    if (k == 13) return;
    const int cnt   = g_cnt[k];
    const int rbase = tile * TILE;
    if (rbase >= cnt) return;

    __shared__ unsigned sAw[64 * RW];
    __shared__ unsigned sBw[96 * RW];
    __shared__ int s_out[TILE];
    __shared__ int s_nin[TILE];

    const int tid = threadIdx.x;
    if (tid < TILE) {
        int i = rbase + tid;
        if (i < cnt) { int2 pr = g_pairs[k * NPTS + i]; s_out[tid] = pr.x; s_nin[tid] = pr.y; }
        else         { s_out[tid] = -1;                 s_nin[tid] = -1; }
    }
    __syncthreads();

    gather_A(sAw, feats, s_nin, tid);
    load_B(sBw, k, tid);
    __syncthreads();

    const int lane = tid & 31, wid = tid >> 5;
    const int wm = wid & 3, wn = wid >> 2;
    float acc[6][4];
    #pragma unroll
    for (int nb = 0; nb < 6; ++nb)
        #pragma unroll
        for (int c = 0; c < 4; ++c) acc[nb][c] = 0.f;

    mma_mainloop(sAw, sBw, acc, lane, wm, wn);

    const int g = lane >> 2, tg = lane & 3;
    const int op0 = s_out[wm * 16 + g], op1 = s_out[wm * 16 + g + 8];
    #pragma unroll
    for (int nb = 0; nb < 6; ++nb) {
        const int col = wn * 48 + nb * 8 + 2 * tg;
        if (op0 >= 0) {
            float* d = g_conv + (size_t)op0 * COUT + col;
            atomicAdd(d,     acc[nb][0]);
            atomicAdd(d + 1, acc[nb][1]);
        }
        if (op1 >= 0) {
            float* d = g_conv + (size_t)op1 * COUT + col;
            atomicAdd(d,     acc[nb][2]);
            atomicAdd(d + 1, acc[nb][3]);
        }
    }
}

// ---------------- 7) LayerNorm + ReLU (one warp per point) -----------------------
__global__ __launch_bounds__(256) void k_ln_relu(const float* __restrict__ gamma,
                                                 const float* __restrict__ beta,
                                                 float* __restrict__ out) {
    const int row  = (blockIdx.x * 256 + threadIdx.x) >> 5;
    const int lane = threadIdx.x & 31;
    const float* src = g_conv + (size_t)row * COUT;
    float v0 = src[lane], v1 = src[lane + 32], v2 = src[lane + 64];
    float s  = v0 + v1 + v2;
    float sq = v0*v0 + v1*v1 + v2*v2;
    #pragma unroll
    for (int o = 16; o > 0; o >>= 1) {
        s  += __shfl_xor_sync(0xffffffffu, s,  o);
        sq += __shfl_xor_sync(0xffffffffu, sq, o);
    }
    float mean = s * (1.f / COUT);
    float var  = sq * (1.f / COUT) - mean * mean;
    float inv  = rsqrtf(var + LN_EPS);
    float* dst = out + (size_t)row * COUT;
    dst[lane]      = fmaxf((v0 - mean) * inv * gamma[lane]      + beta[lane],      0.f);
    dst[lane + 32] = fmaxf((v1 - mean) * inv * gamma[lane + 32] + beta[lane + 32], 0.f);
    dst[lane + 64] = fmaxf((v2 - mean) * inv * gamma[lane + 64] + beta[lane + 64], 0.f);
}

// ---------------- launch ---------------------------------------------------------
extern "C" void kernel_launch(void* const* d_in, const int* in_sizes, int n_in,
                              void* d_out, int out_size) {
    const float* feats  = (const float*)d_in[0];
    const int*   coords = (const int*)  d_in[1];
    const float* weight = (const float*)d_in[2];
    const float* bias   = (const float*)d_in[3];
    const float* gamma  = (const float*)d_in[4];
    const float* beta   = (const float*)d_in[5];
    float* out = (float*)d_out;

    k_init       <<<4096, 256>>>();
    k_scatter    <<<NPTS / 256, 256>>>(coords);
    k_prep_w     <<<(27 * CIN * COUT + 255) / 256, 256>>>(weight);
    k_build_pairs<<<NPTS / 256, 256>>>(coords);
    k_center_gemm<<<TILES_PER_K, 256>>>(feats, coords, bias);
    k_offset_gemm<<<27 * TILES_PER_K, 256>>>(feats);
    k_ln_relu    <<<NPTS / 8, 256>>>(gamma, beta, out);
}

// round 4
// speedup vs baseline: 1.9541x; 1.2468x over previous
#include <cuda_runtime.h>
#include <cuda_bf16.h>

#define GRIDSZ 160
#define GRID3 (GRIDSZ*GRIDSZ*GRIDSZ)
#define NPTS 262144
#define CIN 64
#define COUT 96
#define TILE 64
#define TILES_PER_K 4096
#define LN_EPS 1e-5f
#define MAX_TILES (27 * TILES_PER_K)

// smem row stride in 32-bit words: 32 hi-words + 32 lo-words + 4 pad (68 % 32 == 4)
#define RW 68

// ---------------- scratch (static device globals; no allocation) ----------------
__device__ int   g_grid[GRID3];
__device__ int   g_cnt[27];
__device__ int2  g_pairs[27u * NPTS];
__device__ float g_conv[(size_t)NPTS * COUT];
__device__ __nv_bfloat16 g_wprep[27 * 96 * 128];  // [k][n][hi 0..63 | lo 64..127]
__device__ int   g_ntiles;
__device__ int2  g_tiles[MAX_TILES];              // (k, row_base)

// ---------------- helpers --------------------------------------------------------
__device__ __forceinline__ void split2(float x, float y, unsigned& h, unsigned& l) {
    __nv_bfloat16 hx = __float2bfloat16_rn(x);
    __nv_bfloat16 hy = __float2bfloat16_rn(y);
    float rx = x - __bfloat162float(hx);
    float ry = y - __bfloat162float(hy);
    __nv_bfloat16 lx = __float2bfloat16_rn(rx);
    __nv_bfloat16 ly = __float2bfloat16_rn(ry);
    h = (unsigned)__bfloat16_as_ushort(hx) | ((unsigned)__bfloat16_as_ushort(hy) << 16);
    l = (unsigned)__bfloat16_as_ushort(lx) | ((unsigned)__bfloat16_as_ushort(ly) << 16);
}

__device__ __forceinline__ void mma16816(float* c, unsigned a0, unsigned a1,
                                         unsigned a2, unsigned a3,
                                         unsigned b0, unsigned b1) {
    asm volatile(
        "mma.sync.aligned.m16n8k16.row.col.f32.bf16.bf16.f32 "
        "{%0,%1,%2,%3}, {%4,%5,%6,%7}, {%8,%9}, {%0,%1,%2,%3};"
        : "+f"(c[0]), "+f"(c[1]), "+f"(c[2]), "+f"(c[3])
        : "r"(a0), "r"(a1), "r"(a2), "r"(a3), "r"(b0), "r"(b1));
}

__device__ __forceinline__ void red_add2(float* addr, float a, float b) {
    asm volatile("red.global.add.v2.f32 [%0], {%1, %2};"
                 :: "l"(addr), "f"(a), "f"(b) : "memory");
}

// ---------------- 1) init grid to -1, zero counters ------------------------------
__global__ void k_init() {
    int tid = blockIdx.x * blockDim.x + threadIdx.x;
    if (tid < 27) g_cnt[tid] = 0;
    int4* g4 = (int4*)g_grid;
    const int n4 = GRID3 / 4;
    const int stride = gridDim.x * blockDim.x;
    int4 m1 = make_int4(-1, -1, -1, -1);
    for (int i = tid; i < n4; i += stride) g4[i] = m1;
}

// ---------------- 2) scatter point indices (last-write-wins via atomicMax) -------
__global__ void k_scatter(const int* __restrict__ coords) {
    int i = blockIdx.x * blockDim.x + threadIdx.x;
    if (i < NPTS) {
        int z = coords[3*i+0], y = coords[3*i+1], x = coords[3*i+2];
        atomicMax(&g_grid[(z*GRIDSZ + y)*GRIDSZ + x], i);
    }
}

// ---------------- 3) pre-split weights into bf16 hi/lo planes, n-major -----------
__global__ void k_prep_w(const float* __restrict__ w) {
    int t = blockIdx.x * 256 + threadIdx.x;
    if (t < 27 * CIN * COUT) {
        int k = t / (CIN * COUT);
        int r = t % (CIN * COUT);
        int c = r / COUT;
        int n = r % COUT;
        float x = w[t];
        __nv_bfloat16 hi = __float2bfloat16_rn(x);
        float rx = x - __bfloat162float(hi);
        __nv_bfloat16 lo = __float2bfloat16_rn(rx);
        g_wprep[(k * 96 + n) * 128 + c]      = hi;
        g_wprep[(k * 96 + n) * 128 + 64 + c] = lo;
    }
}

// ---------------- 4) build per-offset pair lists — 2 barriers total ---------------
__global__ __launch_bounds__(256) void k_build_pairs(const int* __restrict__ coords) {
    __shared__ int s_cnt[26][8];
    __shared__ int s_base[26][8];

    const int tid  = threadIdx.x;
    const int p    = blockIdx.x * 256 + tid;
    const int warp = tid >> 5, lane = tid & 31;

    const int z = coords[3*p+0], y = coords[3*p+1], x = coords[3*p+2];

    // hoisted probes (MLP=26)
    int nidx[26];
    #pragma unroll
    for (int j = 0; j < 26; ++j) {
        const int k = (j < 13) ? j : j + 1;
        const int dz = k/9 - 1, dy = (k/3)%3 - 1, dx = k%3 - 1;
        int zz = z + dz, yy = y + dy, xx = x + dx;
        int ni = -1;
        if ((unsigned)zz < GRIDSZ && (unsigned)yy < GRIDSZ && (unsigned)xx < GRIDSZ)
            ni = g_grid[(zz*GRIDSZ + yy)*GRIDSZ + xx];
        nidx[j] = ni;
    }

    // pass 1: per-warp counts for all 26 offsets
    #pragma unroll
    for (int j = 0; j < 26; ++j) {
        unsigned m = __ballot_sync(0xffffffffu, nidx[j] >= 0);
        if (lane == 0) s_cnt[j][warp] = __popc(m);
    }
    __syncthreads();

    // one thread per offset: aggregate 8 warp counts, single atomic, write bases
    if (tid < 26) {
        const int k = (tid < 13) ? tid : tid + 1;
        int c[8], tot = 0;
        #pragma unroll
        for (int w = 0; w < 8; ++w) { c[w] = s_cnt[tid][w]; tot += c[w]; }
        int base = tot ? atomicAdd(&g_cnt[k], tot) : 0;
        #pragma unroll
        for (int w = 0; w < 8; ++w) { s_base[tid][w] = base; base += c[w]; }
    }
    __syncthreads();

    // pass 2: compacted writes
    #pragma unroll
    for (int j = 0; j < 26; ++j) {
        const int k = (j < 13) ? j : j + 1;
        unsigned m = __ballot_sync(0xffffffffu, nidx[j] >= 0);
        if (nidx[j] >= 0) {
            int rank = __popc(m & ((1u << lane) - 1u));
            g_pairs[k * NPTS + s_base[j][warp] + rank] = make_int2(p, nidx[j]);
        }
    }
}

// ---------------- 5) flatten non-empty tiles into a descriptor list ---------------
__global__ void k_make_tiles() {
    __shared__ int s_off[28];
    const int tid = threadIdx.x;
    if (tid < 32) {
        int cnt = (tid < 27) ? g_cnt[tid] : 0;
        int nt  = (cnt + TILE - 1) >> 6;
        int inc = nt;
        #pragma unroll
        for (int o = 1; o < 32; o <<= 1) {
            int v = __shfl_up_sync(0xffffffffu, inc, o);
            if (tid >= o) inc += v;
        }
        if (tid < 27) s_off[tid + 1] = inc;
        if (tid == 0) s_off[0] = 0;
        if (tid == 26) g_ntiles = inc;
    }
    __syncthreads();
    const int total = s_off[27];
    for (int t = tid; t < total; t += blockDim.x) {
        int k = 0;
        while (s_off[k + 1] <= t) ++k;   // 27-entry search
        g_tiles[t] = make_int2(k, (t - s_off[k]) * TILE);
    }
}

// ======================= shared GEMM-tile machinery ==============================
__device__ __forceinline__ void gather_A(unsigned* sAw, const float* __restrict__ feats,
                                         const int* s_nin, int tid) {
    const int row = tid >> 2, q = tid & 3;
    const int ni = s_nin[row];
    unsigned* dh = &sAw[row * RW + q * 8];
    if (ni >= 0) {
        const float4* src = (const float4*)(feats + (size_t)ni * CIN + q * 16);
        #pragma unroll
        for (int j = 0; j < 4; ++j) {
            float4 v = src[j];
            unsigned h0, l0, h1, l1;
            split2(v.x, v.y, h0, l0);
            split2(v.z, v.w, h1, l1);
            dh[2*j]      = h0;
            dh[2*j + 1]  = h1;
            dh[2*j + 32] = l0;
            dh[2*j + 33] = l1;
        }
    } else {
        #pragma unroll
        for (int j = 0; j < 4; ++j) {
            dh[2*j] = 0u; dh[2*j+1] = 0u; dh[2*j+32] = 0u; dh[2*j+33] = 0u;
        }
    }
}

__device__ __forceinline__ void load_B(unsigned* sBw, int k, int tid) {
    const uint4* src = (const uint4*)&g_wprep[(size_t)k * 96 * 128];
    #pragma unroll
    for (int it = 0; it < 6; ++it) {
        int i = tid + it * 256;
        int n = i >> 4, q = i & 15;
        *(uint4*)&sBw[n * RW + q * 4] = src[i];
    }
}

__device__ __forceinline__ void mma_mainloop(const unsigned* sAw, const unsigned* sBw,
                                             float acc[6][4], int lane, int wm, int wn) {
    const int g = lane >> 2, tg = lane & 3;
    const int r0 = wm * 16 + g, r1 = r0 + 8;
    #pragma unroll
    for (int kb = 0; kb < 4; ++kb) {
        const int kw = kb * 8 + tg;
        const unsigned a0h = sAw[r0 * RW + kw],      a1h = sAw[r1 * RW + kw];
        const unsigned a2h = sAw[r0 * RW + kw + 4],  a3h = sAw[r1 * RW + kw + 4];
        const unsigned a0l = sAw[r0 * RW + kw + 32], a1l = sAw[r1 * RW + kw + 32];
        const unsigned a2l = sAw[r0 * RW + kw + 36], a3l = sAw[r1 * RW + kw + 36];
        #pragma unroll
        for (int nb = 0; nb < 6; ++nb) {
            const int n = wn * 48 + nb * 8 + g;
            const unsigned b0h = sBw[n * RW + kw],      b1h = sBw[n * RW + kw + 4];
            const unsigned b0l = sBw[n * RW + kw + 32], b1l = sBw[n * RW + kw + 36];
            mma16816(acc[nb], a0h, a1h, a2h, a3h, b0h, b1h);
            mma16816(acc[nb], a0h, a1h, a2h, a3h, b0l, b1l);
            mma16816(acc[nb], a0l, a1l, a2l, a3l, b0h, b1h);
        }
    }
}

// ---------------- 6) center tap: dense GEMM, plain stores (+bias) -----------------
__global__ __launch_bounds__(256) void k_center_gemm(const float* __restrict__ feats,
                                                     const int*   __restrict__ coords,
                                                     const float* __restrict__ bias) {
    __shared__ unsigned sAw[64 * RW];
    __shared__ unsigned sBw[96 * RW];
    __shared__ int s_nin[TILE];

    const int tid  = threadIdx.x;
    const int base = blockIdx.x * TILE;

    if (tid < TILE) {
        int p = base + tid;
        int z = coords[3*p+0], y = coords[3*p+1], x = coords[3*p+2];
        s_nin[tid] = g_grid[(z*GRIDSZ + y)*GRIDSZ + x];
    }
    __syncthreads();

    gather_A(sAw, feats, s_nin, tid);
    load_B(sBw, 13, tid);
    __syncthreads();

    const int lane = tid & 31, wid = tid >> 5;
    const int wm = wid & 3, wn = wid >> 2;
    float acc[6][4];
    #pragma unroll
    for (int nb = 0; nb < 6; ++nb)
        #pragma unroll
        for (int c = 0; c < 4; ++c) acc[nb][c] = 0.f;

    mma_mainloop(sAw, sBw, acc, lane, wm, wn);

    const int g = lane >> 2, tg = lane & 3;
    const int row0 = base + wm * 16 + g, row1 = row0 + 8;
    #pragma unroll
    for (int nb = 0; nb < 6; ++nb) {
        const int col = wn * 48 + nb * 8 + 2 * tg;
        const float b0 = __ldg(bias + col), b1 = __ldg(bias + col + 1);
        *(float2*)(g_conv + (size_t)row0 * COUT + col) =
            make_float2(acc[nb][0] + b0, acc[nb][1] + b1);
        *(float2*)(g_conv + (size_t)row1 * COUT + col) =
            make_float2(acc[nb][2] + b0, acc[nb][3] + b1);
    }
}

// ---------------- 7) non-center taps: tile-list GEMM, vector red ------------------
__global__ __launch_bounds__(256) void k_offset_gemm(const float* __restrict__ feats) {
    __shared__ unsigned sAw[64 * RW];
    __shared__ unsigned sBw[96 * RW];
    __shared__ int s_out[TILE];
    __shared__ int s_nin[TILE];

    const int tid   = threadIdx.x;
    const int lane  = tid & 31, wid = tid >> 5;
    const int wm    = wid & 3,  wn  = wid >> 2;
    const int total = g_ntiles;

    for (int t = blockIdx.x; t < total; t += gridDim.x) {
        const int2 td   = g_tiles[t];
        const int  k    = td.x;
        const int  rbase = td.y;
        const int  cnt  = g_cnt[k];

        if (tid < TILE) {
            int i = rbase + tid;
            if (i < cnt) { int2 pr = g_pairs[k * NPTS + i]; s_out[tid] = pr.x; s_nin[tid] = pr.y; }
            else         { s_out[tid] = -1;                 s_nin[tid] = -1; }
        }
        __syncthreads();

        gather_A(sAw, feats, s_nin, tid);
        load_B(sBw, k, tid);
        __syncthreads();

        float acc[6][4];
        #pragma unroll
        for (int nb = 0; nb < 6; ++nb)
            #pragma unroll
            for (int c = 0; c < 4; ++c) acc[nb][c] = 0.f;

        mma_mainloop(sAw, sBw, acc, lane, wm, wn);

        const int g = lane >> 2, tg = lane & 3;
        const int op0 = s_out[wm * 16 + g], op1 = s_out[wm * 16 + g + 8];
        #pragma unroll
        for (int nb = 0; nb < 6; ++nb) {
            const int col = wn * 48 + nb * 8 + 2 * tg;
            if (op0 >= 0)
                red_add2(g_conv + (size_t)op0 * COUT + col, acc[nb][0], acc[nb][1]);
            if (op1 >= 0)
                red_add2(g_conv + (size_t)op1 * COUT + col, acc[nb][2], acc[nb][3]);
        }
        __syncthreads();   // protect smem before next tile
    }
}

// ---------------- 8) LayerNorm + ReLU (one warp per point) ------------------------
__global__ __launch_bounds__(256) void k_ln_relu(const float* __restrict__ gamma,
                                                 const float* __restrict__ beta,
                                                 float* __restrict__ out) {
    const int row  = (blockIdx.x * 256 + threadIdx.x) >> 5;
    const int lane = threadIdx.x & 31;
    const float* src = g_conv + (size_t)row * COUT;
    float v0 = src[lane], v1 = src[lane + 32], v2 = src[lane + 64];
    float s  = v0 + v1 + v2;
    float sq = v0*v0 + v1*v1 + v2*v2;
    #pragma unroll
    for (int o = 16; o > 0; o >>= 1) {
        s  += __shfl_xor_sync(0xffffffffu, s,  o);
        sq += __shfl_xor_sync(0xffffffffu, sq, o);
    }
    float mean = s * (1.f / COUT);
    float var  = sq * (1.f / COUT) - mean * mean;
    float inv  = rsqrtf(var + LN_EPS);
    float* dst = out + (size_t)row * COUT;
    dst[lane]      = fmaxf((v0 - mean) * inv * gamma[lane]      + beta[lane],      0.f);
    dst[lane + 32] = fmaxf((v1 - mean) * inv * gamma[lane + 32] + beta[lane + 32], 0.f);
    dst[lane + 64] = fmaxf((v2 - mean) * inv * gamma[lane + 64] + beta[lane + 64], 0.f);
}

// ---------------- launch ----------------------------------------------------------
extern "C" void kernel_launch(void* const* d_in, const int* in_sizes, int n_in,
                              void* d_out, int out_size) {
    const float* feats  = (const float*)d_in[0];
    const int*   coords = (const int*)  d_in[1];
    const float* weight = (const float*)d_in[2];
    const float* bias   = (const float*)d_in[3];
    const float* gamma  = (const float*)d_in[4];
    const float* beta   = (const float*)d_in[5];
    float* out = (float*)d_out;

    k_init       <<<4096, 256>>>();
    k_scatter    <<<NPTS / 256, 256>>>(coords);
    k_prep_w     <<<(27 * CIN * COUT + 255) / 256, 256>>>(weight);
    k_build_pairs<<<NPTS / 256, 256>>>(coords);
    k_make_tiles <<<1, 256>>>();
    k_center_gemm<<<TILES_PER_K, 256>>>(feats, coords, bias);
    k_offset_gemm<<<8192, 256>>>(feats);
    k_ln_relu    <<<NPTS / 8, 256>>>(gamma, beta, out);
}